// round 15
// baseline (speedup 1.0000x reference)
#include <cuda_runtime.h>
#include <cuda_fp16.h>
#include <math.h>
#include <stdint.h>

#define N_EDGES 32000
#define N_NODES 1600
#define HID     128
#define DIN     768
#define M0      7
#define NSPH    49
#define NALL    29
#define WROW    (NSPH * NALL)      // 1421
#define OUT_PER_NODE (NSPH * HID)  // 6272
#define NBLK    (N_EDGES / 128)    // 250

// ---------------- device scratch ---------------------------------------------
static __device__ __align__(256) __half g_x0h[(size_t)N_EDGES * M0 * HID]; // 57MB fp16
static __device__ __align__(16)  float  g_wigc[(size_t)N_EDGES * NSPH * 8]; // 50MB compact
static __device__ int   g_cnt[N_NODES];
static __device__ int   g_off[N_NODES + 1];
static __device__ int   g_cur[N_NODES];
static __device__ int   g_order[N_EDGES];
static __device__ int   g_jidx[M0];
static __device__ float g_jval[M0];
// 28 pre-swizzled fp16 B tiles ([n=128][k=64], SW128 images, 16KB each):
//   0..11 : w1^T   12..13 : w2^T   14..27 : w3^T (7 slabs x 2 k-halves)
static __device__ __align__(1024) __half g_wt16[28 * 8192];
// pre-swizzled fp16 A tiles: [block 250][tile 12][16KB image]
static __device__ __align__(1024) uint4  g_xh4[(size_t)NBLK * 12 * 1024];

// byte swizzle inside a [128 rows x 128B] tile image (SW128)
#define SWZ(b) ((uint32_t)(b) ^ ((((uint32_t)(b)) >> 3) & 0x70))

// ---------------- tiny helpers ------------------------------------------------
__device__ __forceinline__ uint32_t smem_u32(const void* p) {
    uint32_t a;
    asm("{ .reg .u64 t; cvta.to.shared.u64 t, %1; cvt.u32.u64 %0, t; }" : "=r"(a) : "l"(p));
    return a;
}
__device__ __forceinline__ void ffma2(unsigned long long& d,
                                      unsigned long long a, unsigned long long b)
{
    asm("fma.rn.f32x2 %0, %1, %2, %0;" : "+l"(d) : "l"(a), "l"(b));
}
__device__ __forceinline__ unsigned long long packf2(float lo, float hi) {
    unsigned long long u;
    asm("mov.b64 %0, {%1,%2};" : "=l"(u) : "f"(lo), "f"(hi));
    return u;
}
__device__ __forceinline__ float2 unpackf2(unsigned long long u) {
    float lo, hi;
    asm("mov.b64 {%0,%1}, %2;" : "=f"(lo), "=f"(hi) : "l"(u));
    return make_float2(lo, hi);
}

#define LDSM_X4(r0, r1, r2, r3, addr) \
    asm volatile("ldmatrix.sync.aligned.m8n8.x4.shared.b16 {%0,%1,%2,%3}, [%4];" \
        : "=r"(r0), "=r"(r1), "=r"(r2), "=r"(r3) : "r"(addr))

#define MMA16(ac, a0, a1, a2, a3, b0, b1) \
    asm volatile("mma.sync.aligned.m16n8k16.row.col.f32.f16.f16.f32 " \
        "{%0,%1,%2,%3}, {%4,%5,%6,%7}, {%8,%9}, {%0,%1,%2,%3};" \
        : "+f"((ac)[0]), "+f"((ac)[1]), "+f"((ac)[2]), "+f"((ac)[3]) \
        : "r"(a0), "r"(a1), "r"(a2), "r"(a3), "r"(b0), "r"(b1))

__device__ __forceinline__ void cpa16(uint32_t s, const void* g) {
    asm volatile("cp.async.cg.shared.global [%0], [%1], 16;" :: "r"(s), "l"(g));
}
#define CPA_COMMIT() asm volatile("cp.async.commit_group;" ::: "memory")
#define CPA_WAIT2()  asm volatile("cp.async.wait_group 2;" ::: "memory")

// ---------------- prep kernels --------------------------------------------------
__global__ void k_wprep(const float* __restrict__ w1, const float* __restrict__ w2,
                        const float* __restrict__ w3, const float* __restrict__ to_m)
{
    int idx = blockIdx.x * 256 + threadIdx.x;   // 28*8192
    if (idx < N_NODES) g_cnt[idx] = 0;
    if (idx == 0) {
        for (int m = 0; m < M0; m++) {
            int best = 0; float bv = 0.f;
            for (int l = 0; l < NALL; l++) {
                float v = to_m[m * NALL + l];
                if (fabsf(v) > fabsf(bv)) { bv = v; best = l; }
            }
            g_jidx[m] = best;
            g_jval[m] = bv;
        }
    }
    int tile = idx >> 13;
    int r    = idx & 8191;
    int n = r >> 6, k = r & 63;
    float v;
    if (tile < 12)      v = w1[(size_t)(tile * 64 + k) * 128 + n];
    else if (tile < 14) v = w2[(size_t)((tile - 12) * 64 + k) * 128 + n];
    else {
        int mt = tile - 14, m = mt >> 1, hf = mt & 1;
        v = w3[(size_t)(hf * 64 + k) * 896 + m * 128 + n];
    }
    uint32_t byte = SWZ(n * 128 + k * 2);
    *(__half*)((char*)g_wt16 + (size_t)tile * 16384 + byte) = __float2half_rn(v);
}

// compact wigner: [e][49][8] fp32, jval pre-folded, col 7 = 0
__global__ void k_wigc(const float* __restrict__ wig)
{
    int idx = blockIdx.x * 256 + threadIdx.x;   // 32000*49 = 1,568,000
    int e = idx / NSPH, i = idx % NSPH;
    const float* wb = wig + (size_t)e * WROW + i * NALL;
    float4 a, b;
    a.x = wb[g_jidx[0]] * g_jval[0];
    a.y = wb[g_jidx[1]] * g_jval[1];
    a.z = wb[g_jidx[2]] * g_jval[2];
    a.w = wb[g_jidx[3]] * g_jval[3];
    b.x = wb[g_jidx[4]] * g_jval[4];
    b.y = wb[g_jidx[5]] * g_jval[5];
    b.z = wb[g_jidx[6]] * g_jval[6];
    b.w = 0.f;
    float4* d = (float4*)(g_wigc + (size_t)idx * 8);
    d[0] = a; d[1] = b;
}

__global__ void k_xprep(const float* __restrict__ dist, const int* __restrict__ eidx,
                        const int* __restrict__ anum,
                        const float* __restrict__ srcT, const float* __restrict__ tgtT)
{
    int idx = blockIdx.x * 256 + threadIdx.x;   // 32000*96
    int e    = idx / 96;
    int part = idx % 96;
    int col0 = part * 8;
    if (part == 0) atomicAdd(&g_cnt[eidx[N_EDGES + e]], 1);
    float v[8];
    if (col0 < 512) {
        const float4* s = (const float4*)(dist + (size_t)e * 512 + col0);
        float4 x = s[0], y = s[1];
        v[0]=x.x; v[1]=x.y; v[2]=x.z; v[3]=x.w; v[4]=y.x; v[5]=y.y; v[6]=y.z; v[7]=y.w;
    } else if (col0 < 640) {
        int a = anum[eidx[e]];
        const float4* s = (const float4*)(srcT + (size_t)a * 128 + (col0 - 512));
        float4 x = s[0], y = s[1];
        v[0]=x.x; v[1]=x.y; v[2]=x.z; v[3]=x.w; v[4]=y.x; v[5]=y.y; v[6]=y.z; v[7]=y.w;
    } else {
        int a = anum[eidx[N_EDGES + e]];
        const float4* s = (const float4*)(tgtT + (size_t)a * 128 + (col0 - 640));
        float4 x = s[0], y = s[1];
        v[0]=x.x; v[1]=x.y; v[2]=x.z; v[3]=x.w; v[4]=y.x; v[5]=y.y; v[6]=y.z; v[7]=y.w;
    }
    __half2 h[4];
#pragma unroll
    for (int i = 0; i < 4; i++) h[i] = __floats2half2_rn(v[2 * i], v[2 * i + 1]);
    int blk = e >> 7, ti = col0 >> 6;
    uint32_t byte = SWZ((e & 127) * 128 + (col0 & 63) * 2);
    *(uint4*)((char*)g_xh4 + ((size_t)(blk * 12 + ti)) * 16384 + byte) = *(uint4*)h;
}

__global__ void k_scan() {
    __shared__ int s[N_NODES];
    __shared__ int tot[256];
    const int t = threadIdx.x;
    for (int i = t; i < N_NODES; i += 256) s[i] = g_cnt[i];
    __syncthreads();
    const int base = t * 7;
    int sum = 0;
    for (int i = 0; i < 7; i++) {
        int idx = base + i;
        if (idx < N_NODES) { int v = s[idx]; s[idx] = sum; sum += v; }
    }
    tot[t] = sum;
    __syncthreads();
    if (t == 0) {
        int r = 0;
        for (int i = 0; i < 256; i++) { int v = tot[i]; tot[i] = r; r += v; }
        g_off[N_NODES] = r;
    }
    __syncthreads();
    const int b = tot[t];
    for (int i = 0; i < 7; i++) {
        int idx = base + i;
        if (idx < N_NODES) { int o = s[idx] + b; g_off[idx] = o; g_cur[idx] = o; }
    }
}
__global__ void k_scatter(const int* __restrict__ eidx) {
    int e = blockIdx.x * 256 + threadIdx.x;
    int n = eidx[N_EDGES + e];
    int p = atomicAdd(&g_cur[n], 1);
    g_order[p] = e;
}

// ---------------- fp16 mma MLP ----------------------------------------------------
// Warp tiling: warp w covers rows mRow=(w&3)*32 (32 M) x cols nBase=(w>>2)*64 (64 N).
// smem: A ring 3x16KB (slots 0,1 reused for h tiles), B ring 3x16KB, params, LN red.
#define SM_AB   0
#define SM_BB   49152
#define SM_PAR  98304
#define SM_RED  104960
#define SMEM_MLP (104960 + 2048 + 1024)

extern __shared__ float smf[];

__device__ __forceinline__ void compute_tile(uint32_t abase, uint32_t bbase,
                                             float* acc, int mRow, int nBase, int lane)
{
    const int mid = lane >> 3, r8 = lane & 7;
    const uint32_t arow = (uint32_t)((mRow + (mid & 1) * 8 + r8) * 128 + (mid >> 1) * 16);
    const uint32_t brow = (uint32_t)((nBase + (mid >> 1) * 8 + r8) * 128 + (mid & 1) * 16);
#pragma unroll
    for (int ks = 0; ks < 4; ks++) {
        const uint32_t colb = ks * 32;
        uint32_t a00, a01, a02, a03, a10, a11, a12, a13;
        LDSM_X4(a00, a01, a02, a03, abase + SWZ(arow + colb));
        LDSM_X4(a10, a11, a12, a13, abase + SWZ(arow + 16 * 128 + colb));
#pragma unroll
        for (int nc = 0; nc < 4; nc++) {
            uint32_t b0, b1, b2, b3;
            LDSM_X4(b0, b1, b2, b3, bbase + SWZ(brow + nc * 16 * 128 + colb));
            MMA16(acc + (nc * 2    ) * 4, a00, a01, a02, a03, b0, b1);
            MMA16(acc + (nc * 2 + 1) * 4, a00, a01, a02, a03, b2, b3);
            MMA16(acc + (8 + nc * 2    ) * 4, a10, a11, a12, a13, b0, b1);
            MMA16(acc + (8 + nc * 2 + 1) * 4, a10, a11, a12, a13, b2, b3);
        }
    }
}

__global__ __launch_bounds__(256, 2) void k_mlp(
    const float* __restrict__ b1, const float* __restrict__ g1, const float* __restrict__ be1,
    const float* __restrict__ b2, const float* __restrict__ g2, const float* __restrict__ be2,
    const float* __restrict__ b3)
{
    const uint32_t base0 = smem_u32(smf);
    const uint32_t base  = (base0 + 1023) & ~1023u;
    char* smc = (char*)smf + (base - base0);

    const int t    = threadIdx.x;
    const int lane = t & 31;
    const int wid  = t >> 5;
    const int mRow = (wid & 3) * 32;
    const int nBase = (wid >> 2) * 64;
    const int e0   = blockIdx.x * 128;
    const int qr   = lane >> 2, qc = lane & 3;

    const uint32_t ab = base + SM_AB;   // also h tiles (slots 0,1) after GEMM1
    const uint32_t bb = base + SM_BB;
    float*  par  = (float*)(smc + SM_PAR);
    float2* sRed = (float2*)(smc + SM_RED);   // [row][half] partial (s,q)

    if (t < 128) {
        par[t]       = b1[t]; par[128 + t] = g1[t]; par[256 + t] = be1[t];
        par[384 + t] = b2[t]; par[512 + t] = g2[t]; par[640 + t] = be2[t];
    }
    for (int i = t; i < 896; i += 256) par[768 + i] = b3[i];

    auto issueA = [&](int ti, uint32_t buf) {
        const char* src = (const char*)g_xh4 + ((size_t)(blockIdx.x * 12 + ti)) * 16384 + t * 16;
#pragma unroll
        for (int j = 0; j < 4; j++) cpa16(buf + t * 16 + j * 4096, src + j * 4096);
    };
    auto issueB = [&](int ti, uint32_t buf) {
        const char* src = (const char*)g_wt16 + (size_t)ti * 16384 + t * 16;
#pragma unroll
        for (int j = 0; j < 4; j++) cpa16(buf + t * 16 + j * 4096, src + j * 4096);
    };

    // prologue: groups 0,1,2 in flight (group number == tile number)
#pragma unroll
    for (int ti = 0; ti < 3; ti++) {
        issueA(ti, ab + ti * 16384);
        issueB(ti, bb + ti * 16384);
        CPA_COMMIT();
    }

    float acc[64];
#pragma unroll
    for (int i = 0; i < 64; i++) acc[i] = 0.f;

    // LN + SiLU epilogue with cross-warp (2-half) reduction via sRed.
    auto ln_ep = [&](int pbase) {
        float ps[4], pq[4];
#pragma unroll
        for (int mc = 0; mc < 2; mc++)
#pragma unroll
            for (int rh = 0; rh < 2; rh++) {
                float s = 0.f, q = 0.f;
#pragma unroll
                for (int nidx = 0; nidx < 8; nidx++) {
                    const int col = nBase + nidx * 8 + qc * 2;
                    const int gi = (mc * 8 + nidx) * 4 + rh * 2;
                    float v0 = acc[gi]     + par[pbase + col];
                    float v1 = acc[gi + 1] + par[pbase + col + 1];
                    acc[gi] = v0; acc[gi + 1] = v1;
                    s += v0 + v1; q += v0 * v0 + v1 * v1;
                }
                ps[mc * 2 + rh] = s; pq[mc * 2 + rh] = q;
            }
#pragma unroll
        for (int k = 0; k < 4; k++) {
            ps[k] += __shfl_xor_sync(0xffffffffu, ps[k], 1);
            ps[k] += __shfl_xor_sync(0xffffffffu, ps[k], 2);
            pq[k] += __shfl_xor_sync(0xffffffffu, pq[k], 1);
            pq[k] += __shfl_xor_sync(0xffffffffu, pq[k], 2);
        }
        if (qc == 0) {
#pragma unroll
            for (int mc = 0; mc < 2; mc++)
#pragma unroll
                for (int rh = 0; rh < 2; rh++) {
                    const int row = mRow + mc * 16 + rh * 8 + qr;
                    sRed[row * 2 + (nBase >> 6)] = make_float2(ps[mc*2+rh], pq[mc*2+rh]);
                }
        }
        __syncthreads();
        const float inv = 1.f / 128.f;
#pragma unroll
        for (int mc = 0; mc < 2; mc++)
#pragma unroll
            for (int rh = 0; rh < 2; rh++) {
                const int row = mRow + mc * 16 + rh * 8 + qr;
                float2 rA = sRed[row * 2], rB = sRed[row * 2 + 1];
                float mu  = (rA.x + rB.x) * inv;
                float var = (rA.y + rB.y) * inv - mu * mu;
                float rs  = rsqrtf(var + 1e-5f);
                const uint32_t tb = ab + (nBase >> 6) * 16384;
#pragma unroll
                for (int nidx = 0; nidx < 8; nidx++) {
                    const int cl = nidx * 8 + qc * 2;        // col within 64
                    const int col = nBase + cl;
                    const int gi = (mc * 8 + nidx) * 4 + rh * 2;
                    float h0 = (acc[gi]     - mu) * rs * par[pbase + 128 + col] + par[pbase + 256 + col];
                    float h1 = (acc[gi + 1] - mu) * rs * par[pbase + 128 + col + 1] + par[pbase + 256 + col + 1];
                    h0 = h0 / (1.f + __expf(-h0));
                    h1 = h1 / (1.f + __expf(-h1));
                    __half2 p = __floats2half2_rn(h0, h1);
                    asm volatile("st.shared.u32 [%0], %1;"
                        :: "r"(tb + SWZ((uint32_t)(row * 128 + cl * 2))), "r"(*(uint32_t*)&p) : "memory");
                }
            }
#pragma unroll
        for (int i = 0; i < 64; i++) acc[i] = 0.f;
        __syncthreads();
    };

    // ===== unified tile loop: 0..11 GEMM1 | 12..13 GEMM2 | 14..27 GEMM3 =====
    for (int ti = 0; ti < 28; ti++) {
        CPA_WAIT2();
        __syncthreads();
        uint32_t abase;
        if (ti < 12)      abase = ab + (ti % 3) * 16384;
        else if (ti < 14) abase = ab + (ti - 12) * 16384;
        else              abase = ab + ((ti - 14) & 1) * 16384;
        compute_tile(abase, bb + (ti % 3) * 16384, acc, mRow, nBase, lane);
        __syncthreads();
        if (ti + 3 < 28) {
            if (ti + 3 < 12) issueA(ti + 3, ab + ((ti + 3) % 3) * 16384);
            issueB(ti + 3, bb + ((ti + 3) % 3) * 16384);
        }
        CPA_COMMIT();

        if (ti == 11) {
            ln_ep(0);
        } else if (ti == 13) {
            ln_ep(384);
        } else if (ti >= 14 && ((ti - 14) & 1) == 1) {
            const int m = (ti - 14) >> 1;
            // fp16 x0 store, packed uint2: slot (p*4+qc) holds true pairs (2p,2p+1)*4+qc
            const float* bp = par + 768 + m * 128 + nBase;
#pragma unroll
            for (int mc = 0; mc < 2; mc++)
#pragma unroll
                for (int rh = 0; rh < 2; rh++) {
                    const int e = e0 + mRow + mc * 16 + rh * 8 + qr;
                    __half* dst = g_x0h + ((size_t)e * M0 + m) * 128 + nBase;
#pragma unroll
                    for (int p = 0; p < 4; p++) {
                        const int n0 = 2 * p, n1 = 2 * p + 1;
                        const int c0 = n0 * 8 + qc * 2, c1 = n1 * 8 + qc * 2;
                        const int g0 = (mc * 8 + n0) * 4 + rh * 2;
                        const int g1 = (mc * 8 + n1) * 4 + rh * 2;
                        __half2 hA = __floats2half2_rn(acc[g0] + bp[c0], acc[g0+1] + bp[c0+1]);
                        __half2 hB = __floats2half2_rn(acc[g1] + bp[c1], acc[g1+1] + bp[c1+1]);
                        uint2 u; u.x = *(uint32_t*)&hA; u.y = *(uint32_t*)&hB;
                        *(uint2*)(dst + (p * 4 + qc) * 4) = u;
                    }
                }
#pragma unroll
            for (int i = 0; i < 64; i++) acc[i] = 0.f;
        }
    }
}

// ---------------- node-centric wigner contraction + reduce -----------------------
__global__ __launch_bounds__(128, 3) void k_node(
    const float* __restrict__ wig, float* __restrict__ out)
{
    (void)wig;
    __shared__ __align__(16) float2 sW[2][2][NSPH * 8];
    __shared__ __align__(16) float2 sRed[NSPH * 64];

    const int n  = blockIdx.x;
    const int t  = threadIdx.x;
    const int g  = t >> 6;
    const int gt = t & 63;

    const int s0  = g_off[n];
    const int cnt = g_off[n + 1] - s0;
    const int nIter = (cnt + 1) >> 1;

    unsigned long long accu[NSPH];
#pragma unroll
    for (int i = 0; i < NSPH; i++) accu[i] = 0ull;

    int eCur = -1;
    float4  pa, pb;
    __half2 px[7];
    if (g < cnt) {
        eCur = g_order[s0 + g];
        const float4* wp4 = (const float4*)(g_wigc + (size_t)eCur * (NSPH * 8));
        pa = wp4[gt];
        if (gt + 64 < 98) pb = wp4[gt + 64];
        const __half2* x0p = (const __half2*)(g_x0h + (size_t)eCur * M0 * HID) + gt;
#pragma unroll
        for (int m = 0; m < M0; m++) px[m] = x0p[m * 64];
        {
            int i0 = gt >> 1, mq0 = (gt & 1) * 4;
            sW[g][0][i0 * 8 + mq0 + 0] = make_float2(pa.x, pa.x);
            sW[g][0][i0 * 8 + mq0 + 1] = make_float2(pa.y, pa.y);
            sW[g][0][i0 * 8 + mq0 + 2] = make_float2(pa.z, pa.z);
            sW[g][0][i0 * 8 + mq0 + 3] = make_float2(pa.w, pa.w);
            if (gt + 64 < 98) {
                int i1 = (gt + 64) >> 1, mq1 = ((gt + 64) & 1) * 4;
                sW[g][0][i1 * 8 + mq1 + 0] = make_float2(pb.x, pb.x);
                sW[g][0][i1 * 8 + mq1 + 1] = make_float2(pb.y, pb.y);
                sW[g][0][i1 * 8 + mq1 + 2] = make_float2(pb.z, pb.z);
                sW[g][0][i1 * 8 + mq1 + 3] = make_float2(pb.w, pb.w);
            }
        }
    }
    __syncthreads();

    int cur = 0;
    for (int ii = 0; ii < nIter; ii++) {
        const int posn = 2 * (ii + 1) + g;
        int eNext = -1;
        float4  qa, qb;
        __half2 px2[7];
        if (posn < cnt) {
            eNext = g_order[s0 + posn];
            const float4* wp4 = (const float4*)(g_wigc + (size_t)eNext * (NSPH * 8));
            qa = wp4[gt];
            if (gt + 64 < 98) qb = wp4[gt + 64];
            const __half2* x0p = (const __half2*)(g_x0h + (size_t)eNext * M0 * HID) + gt;
#pragma unroll
            for (int m = 0; m < M0; m++) px2[m] = x0p[m * 64];
        }
        if (eCur >= 0) {
            unsigned long long xvu[M0];
#pragma unroll
            for (int m = 0; m < M0; m++) {
                float2 xf = __half22float2(px[m]);
                xvu[m] = packf2(xf.x, xf.y);
            }
            const ulonglong2* wp = (const ulonglong2*)sW[g][cur];
#pragma unroll
            for (int i = 0; i < NSPH; i++) {
                ulonglong2 w01 = wp[i * 4 + 0];
                ulonglong2 w23 = wp[i * 4 + 1];
                ulonglong2 w45 = wp[i * 4 + 2];
                ulonglong2 w6p = wp[i * 4 + 3];
                ffma2(accu[i], w01.x, xvu[0]);
                ffma2(accu[i], w01.y, xvu[1]);
                ffma2(accu[i], w23.x, xvu[2]);
                ffma2(accu[i], w23.y, xvu[3]);
                ffma2(accu[i], w45.x, xvu[4]);
                ffma2(accu[i], w45.y, xvu[5]);
                ffma2(accu[i], w6p.x, xvu[6]);
            }
        }
        __syncthreads();
        if (eNext >= 0) {
            int i0 = gt >> 1, mq0 = (gt & 1) * 4;
            sW[g][cur ^ 1][i0 * 8 + mq0 + 0] = make_float2(qa.x, qa.x);
            sW[g][cur ^ 1][i0 * 8 + mq0 + 1] = make_float2(qa.y, qa.y);
            sW[g][cur ^ 1][i0 * 8 + mq0 + 2] = make_float2(qa.z, qa.z);
            sW[g][cur ^ 1][i0 * 8 + mq0 + 3] = make_float2(qa.w, qa.w);
            if (gt + 64 < 98) {
                int i1 = (gt + 64) >> 1, mq1 = ((gt + 64) & 1) * 4;
                sW[g][cur ^ 1][i1 * 8 + mq1 + 0] = make_float2(qb.x, qb.x);
                sW[g][cur ^ 1][i1 * 8 + mq1 + 1] = make_float2(qb.y, qb.y);
                sW[g][cur ^ 1][i1 * 8 + mq1 + 2] = make_float2(qb.z, qb.z);
                sW[g][cur ^ 1][i1 * 8 + mq1 + 3] = make_float2(qb.w, qb.w);
            }
#pragma unroll
            for (int m = 0; m < M0; m++) px[m] = px2[m];
        }
        __syncthreads();
        cur ^= 1;
        eCur = eNext;
    }

    if (g == 1) {
#pragma unroll
        for (int i = 0; i < NSPH; i++) sRed[i * 64 + gt] = unpackf2(accu[i]);
    }
    __syncthreads();
    if (g == 0) {
        const float sc = (float)(1.0 / 23.395238876342773);
        // storage pair slot gt -> true channel pair c2
        const int c2 = (gt >> 5) * 32 + (2 * ((gt >> 3) & 3) + (gt & 1)) * 4 + ((gt >> 1) & 3);
        float2* outp = (float2*)out;
#pragma unroll
        for (int i = 0; i < NSPH; i++) {
            float2 r = sRed[i * 64 + gt];
            float2 a = unpackf2(accu[i]);
            outp[((size_t)n * NSPH + i) * 64 + c2] =
                make_float2((a.x + r.x) * sc, (a.y + r.y) * sc);
        }
    }
}

// ---------------- launch ----------------------------------------------------------
extern "C" void kernel_launch(void* const* d_in, const int* in_sizes, int n_in,
                              void* d_out, int out_size)
{
    (void)in_sizes; (void)n_in; (void)out_size;
    const int*   anum = (const int*)  d_in[0];
    const float* dist = (const float*)d_in[1];
    const int*   eidx = (const int*)  d_in[2];
    const float* srcT = (const float*)d_in[3];
    const float* tgtT = (const float*)d_in[4];
    const float* w1   = (const float*)d_in[5];
    const float* b1   = (const float*)d_in[6];
    const float* g1   = (const float*)d_in[7];
    const float* be1  = (const float*)d_in[8];
    const float* w2   = (const float*)d_in[9];
    const float* b2   = (const float*)d_in[10];
    const float* g2   = (const float*)d_in[11];
    const float* be2  = (const float*)d_in[12];
    const float* w3   = (const float*)d_in[13];
    const float* b3   = (const float*)d_in[14];
    const float* to_m = (const float*)d_in[15];
    const float* wig  = (const float*)d_in[16];
    float* out = (float*)d_out;

    cudaFuncSetAttribute(k_mlp, cudaFuncAttributeMaxDynamicSharedMemorySize, SMEM_MLP);

    k_wprep<<<28 * 8192 / 256, 256>>>(w1, w2, w3, to_m);
    k_wigc<<<N_EDGES * NSPH / 256, 256>>>(wig);
    k_xprep<<<N_EDGES * 96 / 256, 256>>>(dist, eidx, anum, srcT, tgtT);
    k_scan<<<1, 256>>>();
    k_scatter<<<N_EDGES / 256, 256>>>(eidx);
    k_mlp<<<NBLK, 256, SMEM_MLP>>>(b1, g1, be1, b2, g2, be2, b3);
    k_node<<<N_NODES, 128>>>(wig, out);
}

// round 16
// speedup vs baseline: 1.1018x; 1.1018x over previous
#include <cuda_runtime.h>
#include <cuda_fp16.h>
#include <math.h>
#include <stdint.h>

#define N_EDGES 32000
#define N_NODES 1600
#define HID     128
#define DIN     768
#define M0      7
#define NSPH    49
#define NALL    29
#define WROW    (NSPH * NALL)      // 1421
#define OUT_PER_NODE (NSPH * HID)  // 6272
#define NBLK    (N_EDGES / 128)    // 250
#define CAP     128                // bucket capacity per node

// ---------------- device scratch ---------------------------------------------
static __device__ __align__(256) __half g_x0h[(size_t)N_EDGES * M0 * HID]; // 57MB fp16
static __device__ int   g_cnt[N_NODES];
static __device__ int   g_bkt[N_NODES * CAP];
static __device__ int   g_jidx[M0];
static __device__ float g_jval[M0];
// 28 pre-swizzled fp16 B tiles ([n=128][k=64], SW128 images, 16KB each):
//   0..11 : w1^T   12..13 : w2^T   14..27 : w3^T (7 slabs x 2 k-halves)
static __device__ __align__(1024) __half g_wt16[28 * 8192];
// pre-swizzled fp16 A tiles: [block 250][tile 12][16KB image]
static __device__ __align__(1024) uint4  g_xh4[(size_t)NBLK * 12 * 1024];

// byte swizzle inside a [128 rows x 128B] tile image (SW128)
#define SWZ(b) ((uint32_t)(b) ^ ((((uint32_t)(b)) >> 3) & 0x70))

// ---------------- tiny helpers ------------------------------------------------
__device__ __forceinline__ uint32_t smem_u32(const void* p) {
    uint32_t a;
    asm("{ .reg .u64 t; cvta.to.shared.u64 t, %1; cvt.u32.u64 %0, t; }" : "=r"(a) : "l"(p));
    return a;
}
__device__ __forceinline__ void ffma2(unsigned long long& d,
                                      unsigned long long a, unsigned long long b)
{
    asm("fma.rn.f32x2 %0, %1, %2, %0;" : "+l"(d) : "l"(a), "l"(b));
}
__device__ __forceinline__ unsigned long long packf2(float lo, float hi) {
    unsigned long long u;
    asm("mov.b64 %0, {%1,%2};" : "=l"(u) : "f"(lo), "f"(hi));
    return u;
}
__device__ __forceinline__ float2 unpackf2(unsigned long long u) {
    float lo, hi;
    asm("mov.b64 {%0,%1}, %2;" : "=f"(lo), "=f"(hi) : "l"(u));
    return make_float2(lo, hi);
}

#define LDSM_X4(r0, r1, r2, r3, addr) \
    asm volatile("ldmatrix.sync.aligned.m8n8.x4.shared.b16 {%0,%1,%2,%3}, [%4];" \
        : "=r"(r0), "=r"(r1), "=r"(r2), "=r"(r3) : "r"(addr))

#define MMA16(ac, a0, a1, a2, a3, b0, b1) \
    asm volatile("mma.sync.aligned.m16n8k16.row.col.f32.f16.f16.f32 " \
        "{%0,%1,%2,%3}, {%4,%5,%6,%7}, {%8,%9}, {%0,%1,%2,%3};" \
        : "+f"((ac)[0]), "+f"((ac)[1]), "+f"((ac)[2]), "+f"((ac)[3]) \
        : "r"(a0), "r"(a1), "r"(a2), "r"(a3), "r"(b0), "r"(b1))

__device__ __forceinline__ void cpa16(uint32_t s, const void* g) {
    asm volatile("cp.async.cg.shared.global [%0], [%1], 16;" :: "r"(s), "l"(g));
}
#define CPA_COMMIT() asm volatile("cp.async.commit_group;" ::: "memory")
#define CPA_WAIT2()  asm volatile("cp.async.wait_group 2;" ::: "memory")

// ---------------- prep kernels --------------------------------------------------
__global__ void k_wprep(const float* __restrict__ w1, const float* __restrict__ w2,
                        const float* __restrict__ w3, const float* __restrict__ to_m)
{
    int idx = blockIdx.x * 256 + threadIdx.x;   // 28*8192
    if (idx < N_NODES) g_cnt[idx] = 0;
    if (idx == 0) {
        for (int m = 0; m < M0; m++) {
            int best = 0; float bv = 0.f;
            for (int l = 0; l < NALL; l++) {
                float v = to_m[m * NALL + l];
                if (fabsf(v) > fabsf(bv)) { bv = v; best = l; }
            }
            g_jidx[m] = best;
            g_jval[m] = bv;
        }
    }
    int tile = idx >> 13;
    int r    = idx & 8191;
    int n = r >> 6, k = r & 63;
    float v;
    if (tile < 12)      v = w1[(size_t)(tile * 64 + k) * 128 + n];
    else if (tile < 14) v = w2[(size_t)((tile - 12) * 64 + k) * 128 + n];
    else {
        int mt = tile - 14, m = mt >> 1, hf = mt & 1;
        v = w3[(size_t)(hf * 64 + k) * 896 + m * 128 + n];
    }
    uint32_t byte = SWZ(n * 128 + k * 2);
    *(__half*)((char*)g_wt16 + (size_t)tile * 16384 + byte) = __float2half_rn(v);
}

// gather x -> fp16 SW128 A-tile images; bucket-CSR build in the same pass
__global__ void k_xprep(const float* __restrict__ dist, const int* __restrict__ eidx,
                        const int* __restrict__ anum,
                        const float* __restrict__ srcT, const float* __restrict__ tgtT)
{
    int idx = blockIdx.x * 256 + threadIdx.x;   // 32000*96
    int e    = idx / 96;
    int part = idx % 96;
    int col0 = part * 8;
    if (part == 0) {
        int n = eidx[N_EDGES + e];
        int p = atomicAdd(&g_cnt[n], 1);
        g_bkt[n * CAP + p] = e;
    }
    float v[8];
    if (col0 < 512) {
        const float4* s = (const float4*)(dist + (size_t)e * 512 + col0);
        float4 x = s[0], y = s[1];
        v[0]=x.x; v[1]=x.y; v[2]=x.z; v[3]=x.w; v[4]=y.x; v[5]=y.y; v[6]=y.z; v[7]=y.w;
    } else if (col0 < 640) {
        int a = anum[eidx[e]];
        const float4* s = (const float4*)(srcT + (size_t)a * 128 + (col0 - 512));
        float4 x = s[0], y = s[1];
        v[0]=x.x; v[1]=x.y; v[2]=x.z; v[3]=x.w; v[4]=y.x; v[5]=y.y; v[6]=y.z; v[7]=y.w;
    } else {
        int a = anum[eidx[N_EDGES + e]];
        const float4* s = (const float4*)(tgtT + (size_t)a * 128 + (col0 - 640));
        float4 x = s[0], y = s[1];
        v[0]=x.x; v[1]=x.y; v[2]=x.z; v[3]=x.w; v[4]=y.x; v[5]=y.y; v[6]=y.z; v[7]=y.w;
    }
    __half2 h[4];
#pragma unroll
    for (int i = 0; i < 4; i++) h[i] = __floats2half2_rn(v[2 * i], v[2 * i + 1]);
    int blk = e >> 7, ti = col0 >> 6;
    uint32_t byte = SWZ((e & 127) * 128 + (col0 & 63) * 2);
    *(uint4*)((char*)g_xh4 + ((size_t)(blk * 12 + ti)) * 16384 + byte) = *(uint4*)h;
}

// ---------------- fp16 mma MLP ----------------------------------------------------
#define SM_AB   0
#define SM_BB   49152
#define SM_PAR  98304
#define SMEM_MLP (98304 + 6656 + 1024)

extern __shared__ float smf[];

__device__ __forceinline__ void compute_tile(uint32_t abase, uint32_t bbase,
                                             float* acc, int wRow, int lane)
{
    const int mid = lane >> 3, r8 = lane & 7;
    const uint32_t a_off = (uint32_t)((wRow + (mid & 1) * 8 + r8) * 128 + (mid >> 1) * 16);
    const uint32_t b_hoff = (uint32_t)((mid & 1) * 16);
    const int jadd = mid >> 1;
#pragma unroll
    for (int ks = 0; ks < 4; ks++) {
        const uint32_t colb = ks * 32;
        uint32_t a0, a1, a2, a3;
        LDSM_X4(a0, a1, a2, a3, abase + SWZ(a_off + colb));
#pragma unroll
        for (int j = 0; j < 16; j += 2) {
            uint32_t b0, b1, b2, b3;
            uint32_t baddr = bbase + SWZ((uint32_t)(((j + jadd) * 8 + r8) * 128) + colb + b_hoff);
            LDSM_X4(b0, b1, b2, b3, baddr);
            MMA16(acc + j * 4,       a0, a1, a2, a3, b0, b1);
            MMA16(acc + (j + 1) * 4, a0, a1, a2, a3, b2, b3);
        }
    }
}

__global__ __launch_bounds__(256, 2) void k_mlp(
    const float* __restrict__ b1, const float* __restrict__ g1, const float* __restrict__ be1,
    const float* __restrict__ b2, const float* __restrict__ g2, const float* __restrict__ be2,
    const float* __restrict__ b3)
{
    const uint32_t base0 = smem_u32(smf);
    const uint32_t base  = (base0 + 1023) & ~1023u;
    char* smc = (char*)smf + (base - base0);

    const int t    = threadIdx.x;
    const int lane = t & 31;
    const int wid  = t >> 5;
    const int wRow = wid * 16;
    const int e0   = blockIdx.x * 128;
    const int qr   = lane >> 2, qc = lane & 3;

    const uint32_t ab = base + SM_AB;   // also h tiles (slots 0,1) after GEMM1
    const uint32_t bb = base + SM_BB;
    float* par = (float*)(smc + SM_PAR);

    if (t < 128) {
        par[t]       = b1[t]; par[128 + t] = g1[t]; par[256 + t] = be1[t];
        par[384 + t] = b2[t]; par[512 + t] = g2[t]; par[640 + t] = be2[t];
    }
    for (int i = t; i < 896; i += 256) par[768 + i] = b3[i];

    auto issueA = [&](int ti, uint32_t buf) {
        const char* src = (const char*)g_xh4 + ((size_t)(blockIdx.x * 12 + ti)) * 16384 + t * 16;
#pragma unroll
        for (int j = 0; j < 4; j++) cpa16(buf + t * 16 + j * 4096, src + j * 4096);
    };
    auto issueB = [&](int ti, uint32_t buf) {
        const char* src = (const char*)g_wt16 + (size_t)ti * 16384 + t * 16;
#pragma unroll
        for (int j = 0; j < 4; j++) cpa16(buf + t * 16 + j * 4096, src + j * 4096);
    };

    // prologue: groups 0,1,2 in flight (group number == tile number)
#pragma unroll
    for (int ti = 0; ti < 3; ti++) {
        issueA(ti, ab + ti * 16384);
        issueB(ti, bb + ti * 16384);
        CPA_COMMIT();
    }

    float acc[64];
#pragma unroll
    for (int i = 0; i < 64; i++) acc[i] = 0.f;

    auto ln_ep = [&](int pbase) {
        float s0 = 0.f, q0 = 0.f, s1 = 0.f, q1 = 0.f;
#pragma unroll
        for (int nt = 0; nt < 16; nt++) {
            const int col = nt * 8 + qc * 2;
            float bx = par[pbase + col], by = par[pbase + col + 1];
            float v0 = acc[nt*4+0] + bx, v1 = acc[nt*4+1] + by;
            float v2 = acc[nt*4+2] + bx, v3 = acc[nt*4+3] + by;
            acc[nt*4+0] = v0; acc[nt*4+1] = v1; acc[nt*4+2] = v2; acc[nt*4+3] = v3;
            s0 += v0 + v1; q0 += v0*v0 + v1*v1;
            s1 += v2 + v3; q1 += v2*v2 + v3*v3;
        }
        s0 += __shfl_xor_sync(0xffffffffu, s0, 1); s0 += __shfl_xor_sync(0xffffffffu, s0, 2);
        q0 += __shfl_xor_sync(0xffffffffu, q0, 1); q0 += __shfl_xor_sync(0xffffffffu, q0, 2);
        s1 += __shfl_xor_sync(0xffffffffu, s1, 1); s1 += __shfl_xor_sync(0xffffffffu, s1, 2);
        q1 += __shfl_xor_sync(0xffffffffu, q1, 1); q1 += __shfl_xor_sync(0xffffffffu, q1, 2);
        const float inv = 1.f / 128.f;
        float mu0 = s0 * inv, var0 = q0 * inv - mu0 * mu0, rs0 = rsqrtf(var0 + 1e-5f);
        float mu1 = s1 * inv, var1 = q1 * inv - mu1 * mu1, rs1 = rsqrtf(var1 + 1e-5f);
        const int r0 = wRow + qr, r1 = r0 + 8;
#pragma unroll
        for (int nt = 0; nt < 16; nt++) {
            const int col = nt * 8 + qc * 2;
            float ga = par[pbase + 128 + col], gb = par[pbase + 128 + col + 1];
            float ba = par[pbase + 256 + col], bbv = par[pbase + 256 + col + 1];
            float h0 = (acc[nt*4+0] - mu0) * rs0 * ga + ba;
            float h1 = (acc[nt*4+1] - mu0) * rs0 * gb + bbv;
            float h2 = (acc[nt*4+2] - mu1) * rs1 * ga + ba;
            float h3 = (acc[nt*4+3] - mu1) * rs1 * gb + bbv;
            h0 = h0 / (1.f + __expf(-h0));
            h1 = h1 / (1.f + __expf(-h1));
            h2 = h2 / (1.f + __expf(-h2));
            h3 = h3 / (1.f + __expf(-h3));
            __half2 p0 = __floats2half2_rn(h0, h1);
            __half2 p1 = __floats2half2_rn(h2, h3);
            const uint32_t tb = ab + (col >> 6) * 16384;
            const uint32_t cb = (col & 63) * 2;
            asm volatile("st.shared.u32 [%0], %1;"
                :: "r"(tb + SWZ(r0 * 128 + cb)), "r"(*(uint32_t*)&p0) : "memory");
            asm volatile("st.shared.u32 [%0], %1;"
                :: "r"(tb + SWZ(r1 * 128 + cb)), "r"(*(uint32_t*)&p1) : "memory");
        }
#pragma unroll
        for (int i = 0; i < 64; i++) acc[i] = 0.f;
        __syncthreads();
    };

    // ===== unified tile loop: 0..11 GEMM1 | 12..13 GEMM2 | 14..27 GEMM3 =====
    for (int ti = 0; ti < 28; ti++) {
        CPA_WAIT2();
        __syncthreads();
        uint32_t abase;
        if (ti < 12)      abase = ab + (ti % 3) * 16384;
        else if (ti < 14) abase = ab + (ti - 12) * 16384;
        else              abase = ab + ((ti - 14) & 1) * 16384;
        compute_tile(abase, bb + (ti % 3) * 16384, acc, wRow, lane);
        __syncthreads();
        if (ti + 3 < 28) {
            if (ti + 3 < 12) issueA(ti + 3, ab + ((ti + 3) % 3) * 16384);
            issueB(ti + 3, bb + ((ti + 3) % 3) * 16384);
        }
        CPA_COMMIT();

        if (ti == 11) {
            ln_ep(0);
        } else if (ti == 13) {
            ln_ep(384);
        } else if (ti >= 14 && ((ti - 14) & 1) == 1) {
            const int m = (ti - 14) >> 1;
            // fp16 x0 store, coalesced layout: pos(halves) = j*16 + qc*4
            const size_t eA = (size_t)(e0 + wRow + qr);
            const size_t eB = eA + 8;
            __half* dA = g_x0h + (eA * M0 + m) * 128;
            __half* dB = g_x0h + (eB * M0 + m) * 128;
            const float* bp = par + 768 + m * 128;
#pragma unroll
            for (int j = 0; j < 8; j++) {
                const int ntA = 2 * j, ntB = 2 * j + 1;
                const int cA = ntA * 8 + qc * 2, cB = ntB * 8 + qc * 2;
                __half2 hA = __floats2half2_rn(acc[ntA*4+0] + bp[cA], acc[ntA*4+1] + bp[cA+1]);
                __half2 hB = __floats2half2_rn(acc[ntB*4+0] + bp[cB], acc[ntB*4+1] + bp[cB+1]);
                uint2 u; u.x = *(uint32_t*)&hA; u.y = *(uint32_t*)&hB;
                *(uint2*)(dA + j * 16 + qc * 4) = u;
                __half2 hA2 = __floats2half2_rn(acc[ntA*4+2] + bp[cA], acc[ntA*4+3] + bp[cA+1]);
                __half2 hB2 = __floats2half2_rn(acc[ntB*4+2] + bp[cB], acc[ntB*4+3] + bp[cB+1]);
                uint2 u2; u2.x = *(uint32_t*)&hA2; u2.y = *(uint32_t*)&hB2;
                *(uint2*)(dB + j * 16 + qc * 4) = u2;
            }
#pragma unroll
            for (int i = 0; i < 64; i++) acc[i] = 0.f;
        }
    }
}

// ---------------- node-centric wigner contraction + reduce -----------------------
__global__ __launch_bounds__(128, 3) void k_node(
    const float* __restrict__ wig, float* __restrict__ out)
{
    __shared__ __align__(16) float2 sW[2][2][NSPH * 8];
    __shared__ __align__(16) float2 sRed[NSPH * 64];

    const int n  = blockIdx.x;
    const int t  = threadIdx.x;
    const int g  = t >> 6;
    const int gt = t & 63;

    int   jml[M0];
    float jvl[M0];
#pragma unroll
    for (int m = 0; m < M0; m++) { jml[m] = g_jidx[m]; jvl[m] = g_jval[m]; }

    const int base = n * CAP;
    const int cnt  = g_cnt[n];
    const int nIter = (cnt + 1) >> 1;

    unsigned long long accu[NSPH];
#pragma unroll
    for (int i = 0; i < NSPH; i++) accu[i] = 0ull;

    int eCur = -1;
    float   pv[6];
    __half2 px[7];
    if (g < cnt) {
        eCur = g_bkt[base + g];
        const float* wb = wig + (size_t)eCur * WROW;
#pragma unroll
        for (int j = 0; j < 6; j++) {
            int idx = gt + j * 64;
            if (idx < 343) pv[j] = wb[(idx / 7) * NALL + jml[idx % 7]];
        }
        const __half2* x0p = (const __half2*)(g_x0h + (size_t)eCur * M0 * HID) + gt;
#pragma unroll
        for (int m = 0; m < M0; m++) px[m] = x0p[m * 64];
#pragma unroll
        for (int j = 0; j < 6; j++) {
            int idx = gt + j * 64;
            if (idx < 343) sW[g][0][(idx / 7) * 8 + (idx % 7)] = make_float2(pv[j], pv[j]);
        }
    }
    __syncthreads();

    int cur = 0;
    for (int ii = 0; ii < nIter; ii++) {
        const int posn = 2 * (ii + 1) + g;
        int eNext = -1;
        float   pv2[6];
        __half2 px2[7];
        if (posn < cnt) {
            eNext = g_bkt[base + posn];
            const float* wb = wig + (size_t)eNext * WROW;
#pragma unroll
            for (int j = 0; j < 6; j++) {
                int idx = gt + j * 64;
                if (idx < 343) pv2[j] = wb[(idx / 7) * NALL + jml[idx % 7]];
            }
            const __half2* x0p = (const __half2*)(g_x0h + (size_t)eNext * M0 * HID) + gt;
#pragma unroll
            for (int m = 0; m < M0; m++) px2[m] = x0p[m * 64];
        }
        if (eCur >= 0) {
            unsigned long long xvu[M0];
#pragma unroll
            for (int m = 0; m < M0; m++) {
                float2 xf = __half22float2(px[m]);
                xvu[m] = packf2(xf.x * jvl[m], xf.y * jvl[m]);
            }
            const ulonglong2* wp = (const ulonglong2*)sW[g][cur];
#pragma unroll
            for (int i = 0; i < NSPH; i++) {
                ulonglong2 w01 = wp[i * 4 + 0];
                ulonglong2 w23 = wp[i * 4 + 1];
                ulonglong2 w45 = wp[i * 4 + 2];
                ulonglong2 w6p = wp[i * 4 + 3];
                ffma2(accu[i], w01.x, xvu[0]);
                ffma2(accu[i], w01.y, xvu[1]);
                ffma2(accu[i], w23.x, xvu[2]);
                ffma2(accu[i], w23.y, xvu[3]);
                ffma2(accu[i], w45.x, xvu[4]);
                ffma2(accu[i], w45.y, xvu[5]);
                ffma2(accu[i], w6p.x, xvu[6]);
            }
        }
        __syncthreads();
        if (eNext >= 0) {
#pragma unroll
            for (int j = 0; j < 6; j++) {
                int idx = gt + j * 64;
                if (idx < 343) sW[g][cur ^ 1][(idx / 7) * 8 + (idx % 7)] = make_float2(pv2[j], pv2[j]);
            }
#pragma unroll
            for (int m = 0; m < M0; m++) px[m] = px2[m];
        }
        __syncthreads();
        cur ^= 1;
        eCur = eNext;
    }

    if (g == 1) {
#pragma unroll
        for (int i = 0; i < NSPH; i++) sRed[i * 64 + gt] = unpackf2(accu[i]);
    }
    __syncthreads();
    if (g == 0) {
        const float sc = (float)(1.0 / 23.395238876342773);
        // storage slot gt -> true channel pair c2
        const int c2 = ((gt >> 3) * 2 + (gt & 1)) * 4 + ((gt >> 1) & 3);
        float2* outp = (float2*)out;
#pragma unroll
        for (int i = 0; i < NSPH; i++) {
            float2 r = sRed[i * 64 + gt];
            float2 a = unpackf2(accu[i]);
            outp[((size_t)n * NSPH + i) * 64 + c2] =
                make_float2((a.x + r.x) * sc, (a.y + r.y) * sc);
        }
    }
}

// ---------------- launch ----------------------------------------------------------
extern "C" void kernel_launch(void* const* d_in, const int* in_sizes, int n_in,
                              void* d_out, int out_size)
{
    (void)in_sizes; (void)n_in; (void)out_size;
    const int*   anum = (const int*)  d_in[0];
    const float* dist = (const float*)d_in[1];
    const int*   eidx = (const int*)  d_in[2];
    const float* srcT = (const float*)d_in[3];
    const float* tgtT = (const float*)d_in[4];
    const float* w1   = (const float*)d_in[5];
    const float* b1   = (const float*)d_in[6];
    const float* g1   = (const float*)d_in[7];
    const float* be1  = (const float*)d_in[8];
    const float* w2   = (const float*)d_in[9];
    const float* b2   = (const float*)d_in[10];
    const float* g2   = (const float*)d_in[11];
    const float* be2  = (const float*)d_in[12];
    const float* w3   = (const float*)d_in[13];
    const float* b3   = (const float*)d_in[14];
    const float* to_m = (const float*)d_in[15];
    const float* wig  = (const float*)d_in[16];
    float* out = (float*)d_out;

    cudaFuncSetAttribute(k_mlp, cudaFuncAttributeMaxDynamicSharedMemorySize, SMEM_MLP);

    k_wprep<<<28 * 8192 / 256, 256>>>(w1, w2, w3, to_m);
    k_xprep<<<N_EDGES * 96 / 256, 256>>>(dist, eidx, anum, srcT, tgtT);
    k_mlp<<<NBLK, 256, SMEM_MLP>>>(b1, g1, be1, b2, g2, be2, b3);
    k_node<<<N_NODES, 128>>>(wig, out);
}